// round 15
// baseline (speedup 1.0000x reference)
#include <cuda_runtime.h>
#include <cstdint>
#include <math.h>

#define D_MODEL 768
#define D_INNER 1536
#define D_STATE 16
#define DT_RANK 48
#define D_CONV  4
#define NLAYER  2
#define BATCH   2
#define SEQ     2048
#define NTOK    (BATCH*SEQ)            /* 4096 */
#define XPROJ_N (DT_RANK + 2*D_STATE)  /* 80   */
#define CHUNKS  8
#define CLEN    (SEQ/CHUNKS)           /* 256  */

// ---------------- scratch (device globals: no allocations allowed) ----------
__device__ __align__(16) float g_h [NTOK*D_MODEL];
__device__ __align__(16) float g_xn[NTOK*D_MODEL];
__device__ __align__(16) float g_xz[NTOK*2*D_INNER];
__device__ __align__(16) float g_u [NTOK*D_INNER];
__device__ __align__(16) float g_xd[2*NTOK*XPROJ_N];   // per-layer buffers
__device__ __align__(16) float g_dt[NTOK*D_INNER];
__device__ __align__(16) float g_y [NTOK*D_INNER];
// chunked-scan scratch
__device__ __align__(16) float g_hend [CHUNKS*BATCH*D_INNER*D_STATE];
__device__ __align__(16) float g_r    [CHUNKS*BATCH*D_INNER*D_STATE];
__device__ __align__(16) float g_sumdt[CHUNKS*BATCH*D_INNER];

#define LDSW 132   /* floats per k-row; pad shifts banks, keeps 16B align */

__device__ __forceinline__ float softplus_fast(float v) {
    return (v > 20.f) ? v : __logf(1.f + __expf(v));
}

// ---------------- FFMA TN GEMM: C[M,N] = A[M,K] * W[N,K]^T ------------------
// EPI: 0 none, 1 +bias, 2 softplus(acc+bias), 3 +residual (in-place ok)
// ATOMIC: accumulate into C with atomicAdd (split-K; requires EPI==0)
template <int EPI, bool ATOMIC>
__global__ __launch_bounds__(256, 2)
void fgemm_kernel(const float* __restrict__ A, int lda,
                  const float* __restrict__ W, int ldb,
                  const float* __restrict__ bias,
                  const float* __restrict__ resid,
                  float* __restrict__ C,
                  int N, int K_len)
{
    __shared__ float As[2][16][LDSW];
    __shared__ float Bs[2][16][LDSW];

    const int tid = threadIdx.x;
    const int tx  = tid & 15;          // N-direction
    const int ty  = tid >> 4;          // M-direction (8 rows each)

    const int row0 = blockIdx.y * 128;
    const int col0 = blockIdx.x * 128;
    const int K_begin = blockIdx.z * K_len;

    const int lr  = tid >> 1;
    const int lkb = (tid & 1) * 8;

    float acc[8][8];
    #pragma unroll
    for (int i = 0; i < 8; i++)
        #pragma unroll
        for (int j = 0; j < 8; j++) acc[i][j] = 0.f;

    const int nchunk = K_len >> 4;      // K_len always a multiple of 16
    const float* Ap = A + (size_t)(row0 + lr) * lda + K_begin + lkb;
    const int wcol = col0 + lr;
    const bool bok = (wcol < N);
    const float* Wp = W + (size_t)(bok ? wcol : 0) * ldb + K_begin + lkb;

    float4 av0 = *(const float4*)(Ap);
    float4 av1 = *(const float4*)(Ap + 4);
    float4 bv0 = bok ? *(const float4*)(Wp)     : make_float4(0.f,0.f,0.f,0.f);
    float4 bv1 = bok ? *(const float4*)(Wp + 4) : make_float4(0.f,0.f,0.f,0.f);

    int buf = 0;
    for (int cc = 0; cc < nchunk; cc++) {
        As[buf][lkb+0][lr] = av0.x; As[buf][lkb+1][lr] = av0.y;
        As[buf][lkb+2][lr] = av0.z; As[buf][lkb+3][lr] = av0.w;
        As[buf][lkb+4][lr] = av1.x; As[buf][lkb+5][lr] = av1.y;
        As[buf][lkb+6][lr] = av1.z; As[buf][lkb+7][lr] = av1.w;
        Bs[buf][lkb+0][lr] = bv0.x; Bs[buf][lkb+1][lr] = bv0.y;
        Bs[buf][lkb+2][lr] = bv0.z; Bs[buf][lkb+3][lr] = bv0.w;
        Bs[buf][lkb+4][lr] = bv1.x; Bs[buf][lkb+5][lr] = bv1.y;
        Bs[buf][lkb+6][lr] = bv1.z; Bs[buf][lkb+7][lr] = bv1.w;
        __syncthreads();

        if (cc + 1 < nchunk) {                 // prefetch next tile
            const float* Ap2 = Ap + (cc + 1) * 16;
            const float* Wp2 = Wp + (cc + 1) * 16;
            av0 = *(const float4*)(Ap2);
            av1 = *(const float4*)(Ap2 + 4);
            if (bok) {
                bv0 = *(const float4*)(Wp2);
                bv1 = *(const float4*)(Wp2 + 4);
            }
        }

        #pragma unroll
        for (int kk = 0; kk < 16; kk++) {
            float ar[8], br[8];
            *(float4*)&ar[0] = *(const float4*)&As[buf][kk][ty * 8];
            *(float4*)&ar[4] = *(const float4*)&As[buf][kk][ty * 8 + 4];
            *(float4*)&br[0] = *(const float4*)&Bs[buf][kk][tx * 4];
            *(float4*)&br[4] = *(const float4*)&Bs[buf][kk][64 + tx * 4];
            #pragma unroll
            for (int i = 0; i < 8; i++)
                #pragma unroll
                for (int j = 0; j < 8; j++)
                    acc[i][j] = fmaf(ar[i], br[j], acc[i][j]);
        }
        buf ^= 1;          // single-sync double buffer
    }

    // epilogue: group g=0 -> cols tx*4..+3, g=1 -> cols 64+tx*4..+3
    #pragma unroll
    for (int i = 0; i < 8; i++) {
        const int mrow = row0 + ty * 8 + i;
        #pragma unroll
        for (int g = 0; g < 2; g++) {
            const int c0 = col0 + g * 64 + tx * 4;
            float v[4];
            #pragma unroll
            for (int j = 0; j < 4; j++) v[j] = acc[i][g * 4 + j];
            if (ATOMIC) {
                #pragma unroll
                for (int j = 0; j < 4; j++)
                    if (c0 + j < N) atomicAdd(&C[(size_t)mrow * N + c0 + j], v[j]);
            } else if (c0 + 3 < N) {
                if (EPI == 1) {
                    float4 bb = *(const float4*)(bias + c0);
                    v[0] += bb.x; v[1] += bb.y; v[2] += bb.z; v[3] += bb.w;
                }
                if (EPI == 2) {
                    float4 bb = *(const float4*)(bias + c0);
                    v[0] += bb.x; v[1] += bb.y; v[2] += bb.z; v[3] += bb.w;
                    #pragma unroll
                    for (int j = 0; j < 4; j++)
                        v[j] = softplus_fast(v[j]);
                }
                if (EPI == 3) {
                    float4 rr = *(const float4*)(resid + (size_t)mrow * N + c0);
                    v[0] += rr.x; v[1] += rr.y; v[2] += rr.z; v[3] += rr.w;
                }
                *(float4*)(C + (size_t)mrow * N + c0) =
                    make_float4(v[0], v[1], v[2], v[3]);
            } else {
                #pragma unroll
                for (int j = 0; j < 4; j++) {
                    const int c = c0 + j;
                    if (c < N) {
                        float vv = v[j];
                        if (EPI == 1) vv += bias[c];
                        if (EPI == 2) { vv += bias[c]; vv = softplus_fast(vv); }
                        if (EPI == 3) vv += resid[(size_t)mrow * N + c];
                        C[(size_t)mrow * N + c] = vv;
                    }
                }
            }
        }
    }
}

// ---------------- zero init (for split-K atomic target) ---------------------
__global__ void zero_kernel(float* __restrict__ p, int n)
{
    int i = blockIdx.x * blockDim.x + threadIdx.x;
    if (i < n) p[i] = 0.f;
}

// ---------------- layernorm -------------------------------------------------
__global__ void ln_kernel(const float* __restrict__ in,
                          const float* __restrict__ w,
                          const float* __restrict__ b,
                          float* __restrict__ out)
{
    int row = blockIdx.x;
    const float* xr = in + (size_t)row * D_MODEL;
    float s = 0.f, q = 0.f;
    for (int i = threadIdx.x; i < D_MODEL; i += blockDim.x) {
        float v = xr[i]; s += v; q += v * v;
    }
    __shared__ float sh_s[8], sh_q[8];
    #pragma unroll
    for (int o = 16; o; o >>= 1) {
        s += __shfl_xor_sync(0xffffffffu, s, o);
        q += __shfl_xor_sync(0xffffffffu, q, o);
    }
    int wid = threadIdx.x >> 5;
    if ((threadIdx.x & 31) == 0) { sh_s[wid] = s; sh_q[wid] = q; }
    __syncthreads();
    if (threadIdx.x < 32) {
        s = (threadIdx.x < 8) ? sh_s[threadIdx.x] : 0.f;
        q = (threadIdx.x < 8) ? sh_q[threadIdx.x] : 0.f;
        #pragma unroll
        for (int o = 4; o; o >>= 1) {
            s += __shfl_xor_sync(0xffffffffu, s, o);
            q += __shfl_xor_sync(0xffffffffu, q, o);
        }
        if (threadIdx.x == 0) { sh_s[0] = s; sh_q[0] = q; }
    }
    __syncthreads();
    float mu  = sh_s[0] * (1.f / D_MODEL);
    float var = sh_q[0] * (1.f / D_MODEL) - mu * mu;
    float inv = rsqrtf(var + 1e-5f);
    float* orow = out + (size_t)row * D_MODEL;
    for (int i = threadIdx.x; i < D_MODEL; i += blockDim.x)
        orow[i] = (xr[i] - mu) * inv * w[i] + b[i];
}

// ------------- depthwise causal conv (width 4) + silu, x4 vectorized --------
__global__ void conv_silu_kernel(const float* __restrict__ cw,
                                 const float* __restrict__ cb)
{
    int idx = blockIdx.x * blockDim.x + threadIdx.x;
    if (idx >= NTOK * (D_INNER / 4)) return;
    int d4 = idx % (D_INNER / 4);
    int t  = idx / (D_INNER / 4);
    int l = t % SEQ;
    int b = t / SEQ;
    int d0 = d4 * 4;

    float4 w0 = *(const float4*)(cw + (d0 + 0) * 4);
    float4 w1 = *(const float4*)(cw + (d0 + 1) * 4);
    float4 w2 = *(const float4*)(cw + (d0 + 2) * 4);
    float4 w3 = *(const float4*)(cw + (d0 + 3) * 4);
    float4 acc = *(const float4*)(cb + d0);

    const float* base = g_xz + (size_t)(b * SEQ) * (2 * D_INNER) + d0;
    #pragma unroll
    for (int k = 0; k < D_CONV; k++) {
        int l2 = l - (D_CONV - 1) + k;
        if (l2 >= 0) {
            float4 xv = *(const float4*)(base + (size_t)l2 * (2 * D_INNER));
            float wk0 = (k == 0) ? w0.x : (k == 1) ? w0.y : (k == 2) ? w0.z : w0.w;
            float wk1 = (k == 0) ? w1.x : (k == 1) ? w1.y : (k == 2) ? w1.z : w1.w;
            float wk2 = (k == 0) ? w2.x : (k == 1) ? w2.y : (k == 2) ? w2.z : w2.w;
            float wk3 = (k == 0) ? w3.x : (k == 1) ? w3.y : (k == 2) ? w3.z : w3.w;
            acc.x = fmaf(wk0, xv.x, acc.x);
            acc.y = fmaf(wk1, xv.y, acc.y);
            acc.z = fmaf(wk2, xv.z, acc.z);
            acc.w = fmaf(wk3, xv.w, acc.w);
        }
    }
    acc.x = __fdividef(acc.x, 1.f + __expf(-acc.x));
    acc.y = __fdividef(acc.y, 1.f + __expf(-acc.y));
    acc.z = __fdividef(acc.z, 1.f + __expf(-acc.z));
    acc.w = __fdividef(acc.w, 1.f + __expf(-acc.w));
    *(float4*)(g_u + (size_t)t * D_INNER + d0) = acc;
}

// ================= chunked selective scan ===================================
#define SCH 8
#define STT 32
#define SGRP 8
#define NDG (D_INNER / SCH)    /* 192 channel-groups */

// ---- S1: per-chunk recurrence from h0=0; outputs hend + sum(dt) ------------
__global__ __launch_bounds__(128)
void scan_part1(const float* __restrict__ A_log,
                const float* __restrict__ xd)
{
    __shared__ float s_dt[STT][SCH];
    __shared__ float s_u [STT][SCH];
    __shared__ float s_B [STT][D_STATE];

    const int tid  = threadIdx.x;
    const int w    = tid >> 5;
    const int lane = tid & 31;
    const int s    = lane & 15;
    const int dloc = w * 2 + (lane >> 4);
    int blk = blockIdx.x;
    const int c   = blk / (BATCH * NDG);
    int rem = blk % (BATCH * NDG);
    const int b   = rem / NDG;
    const int d0  = (rem % NDG) * SCH;
    const int d   = d0 + dloc;

    const float Ac = -__expf(A_log[d * D_STATE + s]);
    float h = 0.f, sd = 0.f;
    const size_t tbase = (size_t)b * SEQ + (size_t)c * CLEN;

    for (int t0 = 0; t0 < CLEN; t0 += STT) {
        #pragma unroll
        for (int r = 0; r < 2; r++) {
            int e = tid + r * 128; int tt = e >> 3, j = e & 7;
            size_t t = tbase + t0 + tt;
            s_dt[tt][j] = g_dt[t * D_INNER + d0 + j];
            s_u [tt][j] = g_u [t * D_INNER + d0 + j];
        }
        #pragma unroll
        for (int r = 0; r < 4; r++) {
            int e = tid + r * 128; int tt = e >> 4, j = e & 15;
            size_t t = tbase + t0 + tt;
            s_B[tt][j] = xd[t * XPROJ_N + DT_RANK + j];
        }
        __syncthreads();
        #pragma unroll 8
        for (int tt = 0; tt < STT; tt++) {
            float dt = s_dt[tt][dloc];
            float u  = s_u [tt][dloc];
            h = fmaf(__expf(dt * Ac), h, dt * u * s_B[tt][s]);
            sd += dt;
        }
        __syncthreads();
    }
    size_t idx = (((size_t)c * BATCH + b) * D_INNER + d) * D_STATE + s;
    g_hend[idx] = h;
    if (s == 0)
        g_sumdt[((size_t)c * BATCH + b) * D_INNER + d] = sd;
}

// ---- S2: sequential chunk fixup ---------------------------------------------
__global__ void scan_fixup(const float* __restrict__ A_log)
{
    int i = blockIdx.x * blockDim.x + threadIdx.x;
    if (i >= BATCH * D_INNER * D_STATE) return;
    const int s = i & 15;
    const int d = (i >> 4) % D_INNER;
    const int b = (i >> 4) / D_INNER;
    const float Ac = -__expf(A_log[d * D_STATE + s]);
    float r = 0.f;
    #pragma unroll
    for (int c = 0; c < CHUNKS; c++) {
        g_r[(((size_t)c * BATCH + b) * D_INNER + d) * D_STATE + s] = r;
        if (c + 1 < CHUNKS) {
            size_t idx = (((size_t)c * BATCH + b) * D_INNER + d) * D_STATE + s;
            float P = __expf(Ac * g_sumdt[((size_t)c * BATCH + b) * D_INNER + d]);
            r = fmaf(P, r, g_hend[idx]);
        }
    }
}

// ---- S3: full scan per chunk seeded with h0=r_c -----------------------------
__global__ __launch_bounds__(128)
void scan_part3(const float* __restrict__ A_log,
                const float* __restrict__ Dp,
                const float* __restrict__ xd)
{
    __shared__ float s_dt[STT][SCH];
    __shared__ float s_u [STT][SCH];
    __shared__ float s_z [STT][SCH];
    __shared__ float s_B [STT][D_STATE];
    __shared__ float s_C [STT][D_STATE];
    __shared__ float s_out[4][2][SGRP];

    const int tid  = threadIdx.x;
    const int w    = tid >> 5;
    const int lane = tid & 31;
    const int s    = lane & 15;
    const int dloc = w * 2 + (lane >> 4);
    int blk = blockIdx.x;
    const int c   = blk / (BATCH * NDG);
    int rem = blk % (BATCH * NDG);
    const int b   = rem / NDG;
    const int d0  = (rem % NDG) * SCH;
    const int d   = d0 + dloc;

    const float Ac  = -__expf(A_log[d * D_STATE + s]);
    const float Dv0 = Dp[d0 + w * 2];
    const float Dv1 = Dp[d0 + w * 2 + 1];
    float h = g_r[(((size_t)c * BATCH + b) * D_INNER + d) * D_STATE + s];

    const size_t tbase = (size_t)b * SEQ + (size_t)c * CLEN;

    float r_dt[2], r_u[2], r_z[2], r_bc[8];
    int st_tt[2], st_j[2], bc_tt[8], bc_j[8];
    #pragma unroll
    for (int r = 0; r < 2; r++) {
        int e = tid + r * 128; st_tt[r] = e >> 3; st_j[r] = e & 7;
    }
    #pragma unroll
    for (int r = 0; r < 8; r++) {
        int e = tid + r * 128; bc_tt[r] = e >> 5; bc_j[r] = e & 31;
    }

    #pragma unroll
    for (int r = 0; r < 2; r++) {
        size_t t = tbase + st_tt[r];
        r_dt[r] = g_dt[t * D_INNER + d0 + st_j[r]];
        r_u [r] = g_u [t * D_INNER + d0 + st_j[r]];
        r_z [r] = g_xz[t * (2 * D_INNER) + D_INNER + d0 + st_j[r]];
    }
    #pragma unroll
    for (int r = 0; r < 8; r++) {
        size_t t = tbase + bc_tt[r];
        r_bc[r] = xd[t * XPROJ_N + DT_RANK + bc_j[r]];
    }

    for (int t0 = 0; t0 < CLEN; t0 += STT) {
        #pragma unroll
        for (int r = 0; r < 2; r++) {
            s_dt[st_tt[r]][st_j[r]] = r_dt[r];
            s_u [st_tt[r]][st_j[r]] = r_u [r];
            s_z [st_tt[r]][st_j[r]] = r_z [r];
        }
        #pragma unroll
        for (int r = 0; r < 8; r++) {
            if (bc_j[r] < D_STATE) s_B[bc_tt[r]][bc_j[r]] = r_bc[r];
            else                   s_C[bc_tt[r]][bc_j[r] - D_STATE] = r_bc[r];
        }
        __syncthreads();

        if (t0 + STT < CLEN) {
            #pragma unroll
            for (int r = 0; r < 2; r++) {
                size_t t = tbase + t0 + STT + st_tt[r];
                r_dt[r] = g_dt[t * D_INNER + d0 + st_j[r]];
                r_u [r] = g_u [t * D_INNER + d0 + st_j[r]];
                r_z [r] = g_xz[t * (2 * D_INNER) + D_INNER + d0 + st_j[r]];
            }
            #pragma unroll
            for (int r = 0; r < 8; r++) {
                size_t t = tbase + t0 + STT + bc_tt[r];
                r_bc[r] = xd[t * XPROJ_N + DT_RANK + bc_j[r]];
            }
        }

        #pragma unroll
        for (int g = 0; g < STT / SGRP; g++) {
            float pb[SGRP];
            #pragma unroll
            for (int q = 0; q < SGRP; q++) {
                const int tt = g * SGRP + q;
                float dt = s_dt[tt][dloc];
                float u  = s_u [tt][dloc];
                h = fmaf(__expf(dt * Ac), h, dt * u * s_B[tt][s]);
                pb[q] = h * s_C[tt][s];
            }
            #pragma unroll
            for (int q = 0; q < SGRP; q++)
                pb[q] += __shfl_xor_sync(0xffffffffu, pb[q], 8);
            #pragma unroll
            for (int q = 0; q < SGRP; q++)
                pb[q] += __shfl_xor_sync(0xffffffffu, pb[q], 4);
            #pragma unroll
            for (int q = 0; q < SGRP; q++)
                pb[q] += __shfl_xor_sync(0xffffffffu, pb[q], 2);
            #pragma unroll
            for (int q = 0; q < SGRP; q++)
                pb[q] += __shfl_xor_sync(0xffffffffu, pb[q], 1);
            if (s == 0) {
                const int cc = lane >> 4;
                #pragma unroll
                for (int q = 0; q < SGRP; q++) s_out[w][cc][q] = pb[q];
            }
            __syncwarp();
            if (lane < 16) {
                const int c2 = lane >> 3, q2 = lane & 7;
                const int tt = g * SGRP + q2;
                const int dl = w * 2 + c2;
                float val = s_out[w][c2][q2];
                float u2  = s_u[tt][dl];
                float z2  = s_z[tt][dl];
                float Dv2 = c2 ? Dv1 : Dv0;
                float sil = __fdividef(z2, 1.f + __expf(-z2));
                g_y[(tbase + t0 + tt) * D_INNER + d0 + dl] =
                    (val + u2 * Dv2) * sil;
            }
            __syncwarp();
        }
        __syncthreads();
    }
}

// ---------------- host orchestration ----------------------------------------
extern "C" void kernel_launch(void* const* d_in, const int* in_sizes, int n_in,
                              void* d_out, int out_size)
{
    const float* x         = (const float*)d_in[0];
    const float* in_proj_w = (const float*)d_in[1];
    const float* conv_w    = (const float*)d_in[2];
    const float* conv_b    = (const float*)d_in[3];
    const float* x_proj_w  = (const float*)d_in[4];
    const float* dt_proj_w = (const float*)d_in[5];
    const float* dt_proj_b = (const float*)d_in[6];
    const float* A_log     = (const float*)d_in[7];
    const float* D_param   = (const float*)d_in[8];
    const float* out_proj_w= (const float*)d_in[9];
    const float* ln_w      = (const float*)d_in[10];
    const float* ln_b      = (const float*)d_in[11];
    const float* fnorm_w   = (const float*)d_in[12];
    const float* fnorm_b   = (const float*)d_in[13];
    const float* proj_w    = (const float*)d_in[14];
    const float* proj_b    = (const float*)d_in[15];

    float *h, *xn, *xz, *u, *xd, *dt, *y;
    cudaGetSymbolAddress((void**)&h,  g_h);
    cudaGetSymbolAddress((void**)&xn, g_xn);
    cudaGetSymbolAddress((void**)&xz, g_xz);
    cudaGetSymbolAddress((void**)&u,  g_u);
    cudaGetSymbolAddress((void**)&xd, g_xd);
    cudaGetSymbolAddress((void**)&dt, g_dt);
    cudaGetSymbolAddress((void**)&y,  g_y);

    const int xd_half = NTOK * XPROJ_N;

    cudaMemcpyAsync(h, x, sizeof(float) * (size_t)NTOK * D_MODEL,
                    cudaMemcpyDeviceToDevice);
    zero_kernel<<<(xd_half + 255) / 256, 256>>>(xd, xd_half);
    zero_kernel<<<(xd_half + 255) / 256, 256>>>(xd + xd_half, xd_half);

    dim3 gIn (2 * D_INNER / 128, NTOK / 128, 1);   // 24 x 32
    dim3 gXp (1,                 NTOK / 128, 6);   // N=80, split-K x6
    dim3 gDt (D_INNER / 128,     NTOK / 128, 1);   // 12 x 32
    dim3 gOut(D_MODEL / 128,     NTOK / 128, 1);   //  6 x 32
    const int gScan = CHUNKS * BATCH * NDG;        // 3072

    for (int i = 0; i < NLAYER; i++) {
        float* xdi = xd + (size_t)i * xd_half;
        const float* Ai = A_log + (size_t)i * D_INNER * D_STATE;

        ln_kernel<<<NTOK, 256>>>(h, ln_w + i * D_MODEL, ln_b + i * D_MODEL, xn);

        fgemm_kernel<0, false><<<gIn, 256>>>(
            xn, D_MODEL,
            in_proj_w + (size_t)i * 2 * D_INNER * D_MODEL, D_MODEL,
            nullptr, nullptr, xz, 2 * D_INNER, D_MODEL);

        conv_silu_kernel<<<(NTOK * (D_INNER / 4) + 255) / 256, 256>>>(
            conv_w + (size_t)i * D_INNER * D_CONV, conv_b + i * D_INNER);

        fgemm_kernel<0, true><<<gXp, 256>>>(
            u, D_INNER,
            x_proj_w + (size_t)i * XPROJ_N * D_INNER, D_INNER,
            nullptr, nullptr, xdi, XPROJ_N, D_INNER / 6);

        fgemm_kernel<2, false><<<gDt, 256>>>(
            xdi, XPROJ_N,
            dt_proj_w + (size_t)i * D_INNER * DT_RANK, DT_RANK,
            dt_proj_b + i * D_INNER, nullptr, dt, D_INNER, DT_RANK);

        scan_part1<<<gScan, 128>>>(Ai, xdi);
        scan_fixup<<<(BATCH * D_INNER * D_STATE + 255) / 256, 256>>>(Ai);
        scan_part3<<<gScan, 128>>>(Ai, D_param + i * D_INNER, xdi);

        fgemm_kernel<3, false><<<gOut, 256>>>(
            y, D_INNER,
            out_proj_w + (size_t)i * D_MODEL * D_INNER, D_INNER,
            nullptr, h, h, D_MODEL, D_INNER);
    }

    ln_kernel<<<NTOK, 256>>>(h, fnorm_w, fnorm_b, xn);

    fgemm_kernel<1, false><<<gOut, 256>>>(
        xn, D_MODEL, proj_w, D_MODEL, proj_b, nullptr,
        (float*)d_out, D_MODEL, D_MODEL);
}

// round 16
// speedup vs baseline: 1.0412x; 1.0412x over previous
#include <cuda_runtime.h>
#include <cstdint>
#include <math.h>

#define D_MODEL 768
#define D_INNER 1536
#define D_STATE 16
#define DT_RANK 48
#define D_CONV  4
#define NLAYER  2
#define BATCH   2
#define SEQ     2048
#define NTOK    (BATCH*SEQ)            /* 4096 */
#define XPROJ_N (DT_RANK + 2*D_STATE)  /* 80   */
#define CHUNKS  8
#define CLEN    (SEQ/CHUNKS)           /* 256  */

// ---------------- scratch (device globals: no allocations allowed) ----------
__device__ __align__(16) float g_h [NTOK*D_MODEL];
__device__ __align__(16) float g_xn[NTOK*D_MODEL];
__device__ __align__(16) float g_xz[NTOK*2*D_INNER];
__device__ __align__(16) float g_u [NTOK*D_INNER];
__device__ __align__(16) float g_xd[2*NTOK*XPROJ_N];   // per-layer buffers
__device__ __align__(16) float g_dt[NTOK*D_INNER];
__device__ __align__(16) float g_y [NTOK*D_INNER];
// chunked-scan scratch
__device__ __align__(16) float g_hend [CHUNKS*BATCH*D_INNER*D_STATE];
__device__ __align__(16) float g_r    [CHUNKS*BATCH*D_INNER*D_STATE];
__device__ __align__(16) float g_sumdt[CHUNKS*BATCH*D_INNER];

#define LDSW 132   /* floats per k-row; pad shifts banks, keeps 16B align */

__device__ __forceinline__ float softplus_fast(float v) {
    return (v > 20.f) ? v : __logf(1.f + __expf(v));
}

// ---------------- FFMA TN GEMM: C[M,N] = A[M,K] * W[N,K]^T ------------------
// EPI: 0 none, 1 +bias, 2 softplus(acc+bias), 3 +residual (in-place ok)
// ATOMIC: accumulate into C with atomicAdd (split-K; requires EPI==0)
template <int EPI, bool ATOMIC>
__global__ __launch_bounds__(256, 2)
void fgemm_kernel(const float* __restrict__ A, int lda,
                  const float* __restrict__ W, int ldb,
                  const float* __restrict__ bias,
                  const float* __restrict__ resid,
                  float* __restrict__ C,
                  int N, int K_len)
{
    __shared__ float As[2][16][LDSW];
    __shared__ float Bs[2][16][LDSW];

    const int tid = threadIdx.x;
    const int tx  = tid & 15;          // N-direction
    const int ty  = tid >> 4;          // M-direction (8 rows each)

    const int row0 = blockIdx.y * 128;
    const int col0 = blockIdx.x * 128;
    const int K_begin = blockIdx.z * K_len;

    const int lr  = tid >> 1;
    const int lkb = (tid & 1) * 8;

    float acc[8][8];
    #pragma unroll
    for (int i = 0; i < 8; i++)
        #pragma unroll
        for (int j = 0; j < 8; j++) acc[i][j] = 0.f;

    const int nchunk = K_len >> 4;      // K_len always a multiple of 16
    const float* Ap = A + (size_t)(row0 + lr) * lda + K_begin + lkb;
    const int wcol = col0 + lr;
    const bool bok = (wcol < N);
    const float* Wp = W + (size_t)(bok ? wcol : 0) * ldb + K_begin + lkb;

    float4 av0 = *(const float4*)(Ap);
    float4 av1 = *(const float4*)(Ap + 4);
    float4 bv0 = bok ? *(const float4*)(Wp)     : make_float4(0.f,0.f,0.f,0.f);
    float4 bv1 = bok ? *(const float4*)(Wp + 4) : make_float4(0.f,0.f,0.f,0.f);

    int buf = 0;
    for (int cc = 0; cc < nchunk; cc++) {
        As[buf][lkb+0][lr] = av0.x; As[buf][lkb+1][lr] = av0.y;
        As[buf][lkb+2][lr] = av0.z; As[buf][lkb+3][lr] = av0.w;
        As[buf][lkb+4][lr] = av1.x; As[buf][lkb+5][lr] = av1.y;
        As[buf][lkb+6][lr] = av1.z; As[buf][lkb+7][lr] = av1.w;
        Bs[buf][lkb+0][lr] = bv0.x; Bs[buf][lkb+1][lr] = bv0.y;
        Bs[buf][lkb+2][lr] = bv0.z; Bs[buf][lkb+3][lr] = bv0.w;
        Bs[buf][lkb+4][lr] = bv1.x; Bs[buf][lkb+5][lr] = bv1.y;
        Bs[buf][lkb+6][lr] = bv1.z; Bs[buf][lkb+7][lr] = bv1.w;
        __syncthreads();

        if (cc + 1 < nchunk) {                 // prefetch next tile
            const float* Ap2 = Ap + (cc + 1) * 16;
            const float* Wp2 = Wp + (cc + 1) * 16;
            av0 = *(const float4*)(Ap2);
            av1 = *(const float4*)(Ap2 + 4);
            if (bok) {
                bv0 = *(const float4*)(Wp2);
                bv1 = *(const float4*)(Wp2 + 4);
            }
        }

        #pragma unroll
        for (int kk = 0; kk < 16; kk++) {
            float ar[8], br[8];
            *(float4*)&ar[0] = *(const float4*)&As[buf][kk][ty * 8];
            *(float4*)&ar[4] = *(const float4*)&As[buf][kk][ty * 8 + 4];
            *(float4*)&br[0] = *(const float4*)&Bs[buf][kk][tx * 4];
            *(float4*)&br[4] = *(const float4*)&Bs[buf][kk][64 + tx * 4];
            #pragma unroll
            for (int i = 0; i < 8; i++)
                #pragma unroll
                for (int j = 0; j < 8; j++)
                    acc[i][j] = fmaf(ar[i], br[j], acc[i][j]);
        }
        buf ^= 1;          // single-sync double buffer
    }

    // epilogue: group g=0 -> cols tx*4..+3, g=1 -> cols 64+tx*4..+3
    #pragma unroll
    for (int i = 0; i < 8; i++) {
        const int mrow = row0 + ty * 8 + i;
        #pragma unroll
        for (int g = 0; g < 2; g++) {
            const int c0 = col0 + g * 64 + tx * 4;
            float v[4];
            #pragma unroll
            for (int j = 0; j < 4; j++) v[j] = acc[i][g * 4 + j];
            if (ATOMIC) {
                #pragma unroll
                for (int j = 0; j < 4; j++)
                    if (c0 + j < N) atomicAdd(&C[(size_t)mrow * N + c0 + j], v[j]);
            } else if (c0 + 3 < N) {
                if (EPI == 1) {
                    float4 bb = *(const float4*)(bias + c0);
                    v[0] += bb.x; v[1] += bb.y; v[2] += bb.z; v[3] += bb.w;
                }
                if (EPI == 2) {
                    float4 bb = *(const float4*)(bias + c0);
                    v[0] += bb.x; v[1] += bb.y; v[2] += bb.z; v[3] += bb.w;
                    #pragma unroll
                    for (int j = 0; j < 4; j++)
                        v[j] = softplus_fast(v[j]);
                }
                if (EPI == 3) {
                    float4 rr = *(const float4*)(resid + (size_t)mrow * N + c0);
                    v[0] += rr.x; v[1] += rr.y; v[2] += rr.z; v[3] += rr.w;
                }
                *(float4*)(C + (size_t)mrow * N + c0) =
                    make_float4(v[0], v[1], v[2], v[3]);
            } else {
                #pragma unroll
                for (int j = 0; j < 4; j++) {
                    const int c = c0 + j;
                    if (c < N) {
                        float vv = v[j];
                        if (EPI == 1) vv += bias[c];
                        if (EPI == 2) { vv += bias[c]; vv = softplus_fast(vv); }
                        if (EPI == 3) vv += resid[(size_t)mrow * N + c];
                        C[(size_t)mrow * N + c] = vv;
                    }
                }
            }
        }
    }
}

// ---------------- zero init (for split-K atomic target) ---------------------
__global__ void zero_kernel(float* __restrict__ p, int n)
{
    int i = blockIdx.x * blockDim.x + threadIdx.x;
    if (i < n) p[i] = 0.f;
}

// ---------------- layernorm -------------------------------------------------
__global__ void ln_kernel(const float* __restrict__ in,
                          const float* __restrict__ w,
                          const float* __restrict__ b,
                          float* __restrict__ out)
{
    int row = blockIdx.x;
    const float* xr = in + (size_t)row * D_MODEL;
    float s = 0.f, q = 0.f;
    for (int i = threadIdx.x; i < D_MODEL; i += blockDim.x) {
        float v = xr[i]; s += v; q += v * v;
    }
    __shared__ float sh_s[8], sh_q[8];
    #pragma unroll
    for (int o = 16; o; o >>= 1) {
        s += __shfl_xor_sync(0xffffffffu, s, o);
        q += __shfl_xor_sync(0xffffffffu, q, o);
    }
    int wid = threadIdx.x >> 5;
    if ((threadIdx.x & 31) == 0) { sh_s[wid] = s; sh_q[wid] = q; }
    __syncthreads();
    if (threadIdx.x < 32) {
        s = (threadIdx.x < 8) ? sh_s[threadIdx.x] : 0.f;
        q = (threadIdx.x < 8) ? sh_q[threadIdx.x] : 0.f;
        #pragma unroll
        for (int o = 4; o; o >>= 1) {
            s += __shfl_xor_sync(0xffffffffu, s, o);
            q += __shfl_xor_sync(0xffffffffu, q, o);
        }
        if (threadIdx.x == 0) { sh_s[0] = s; sh_q[0] = q; }
    }
    __syncthreads();
    float mu  = sh_s[0] * (1.f / D_MODEL);
    float var = sh_q[0] * (1.f / D_MODEL) - mu * mu;
    float inv = rsqrtf(var + 1e-5f);
    float* orow = out + (size_t)row * D_MODEL;
    for (int i = threadIdx.x; i < D_MODEL; i += blockDim.x)
        orow[i] = (xr[i] - mu) * inv * w[i] + b[i];
}

// ------------- depthwise causal conv (width 4) + silu, x4 vectorized --------
__global__ void conv_silu_kernel(const float* __restrict__ cw,
                                 const float* __restrict__ cb)
{
    int idx = blockIdx.x * blockDim.x + threadIdx.x;
    if (idx >= NTOK * (D_INNER / 4)) return;
    int d4 = idx % (D_INNER / 4);
    int t  = idx / (D_INNER / 4);
    int l = t % SEQ;
    int b = t / SEQ;
    int d0 = d4 * 4;

    float4 w0 = *(const float4*)(cw + (d0 + 0) * 4);
    float4 w1 = *(const float4*)(cw + (d0 + 1) * 4);
    float4 w2 = *(const float4*)(cw + (d0 + 2) * 4);
    float4 w3 = *(const float4*)(cw + (d0 + 3) * 4);
    float4 acc = *(const float4*)(cb + d0);

    const float* base = g_xz + (size_t)(b * SEQ) * (2 * D_INNER) + d0;
    #pragma unroll
    for (int k = 0; k < D_CONV; k++) {
        int l2 = l - (D_CONV - 1) + k;
        if (l2 >= 0) {
            float4 xv = *(const float4*)(base + (size_t)l2 * (2 * D_INNER));
            float wk0 = (k == 0) ? w0.x : (k == 1) ? w0.y : (k == 2) ? w0.z : w0.w;
            float wk1 = (k == 0) ? w1.x : (k == 1) ? w1.y : (k == 2) ? w1.z : w1.w;
            float wk2 = (k == 0) ? w2.x : (k == 1) ? w2.y : (k == 2) ? w2.z : w2.w;
            float wk3 = (k == 0) ? w3.x : (k == 1) ? w3.y : (k == 2) ? w3.z : w3.w;
            acc.x = fmaf(wk0, xv.x, acc.x);
            acc.y = fmaf(wk1, xv.y, acc.y);
            acc.z = fmaf(wk2, xv.z, acc.z);
            acc.w = fmaf(wk3, xv.w, acc.w);
        }
    }
    acc.x = __fdividef(acc.x, 1.f + __expf(-acc.x));
    acc.y = __fdividef(acc.y, 1.f + __expf(-acc.y));
    acc.z = __fdividef(acc.z, 1.f + __expf(-acc.z));
    acc.w = __fdividef(acc.w, 1.f + __expf(-acc.w));
    *(float4*)(g_u + (size_t)t * D_INNER + d0) = acc;
}

// ============ chunked selective scan, v5c lane layout =======================
// lane: q = state group (0..3, states q*4..q*4+3), chl = lane>>2 (8 ch/warp)
// block = 128 thr = 4 warps = 32 channels; grid = CHUNKS*BATCH*48 = 768
#define SCB 32
#define STT 32
#define NCG (D_INNER / SCB)    /* 48 channel-groups */

// ---- S1: per-chunk recurrence from h0=0; outputs hend (4/lane) + sum(dt) ---
__global__ __launch_bounds__(128)
void scan_part1(const float* __restrict__ A_log,
                const float* __restrict__ xd)
{
    __shared__ __align__(16) float s_dt[STT][SCB];
    __shared__ __align__(16) float s_u [STT][SCB];
    __shared__ __align__(16) float s_B [STT][D_STATE];

    const int tid  = threadIdx.x;
    const int w    = tid >> 5;
    const int lane = tid & 31;
    const int q    = lane & 3;
    const int chl  = lane >> 2;
    const int dloc = w * 8 + chl;
    const int c    = blockIdx.x / (BATCH * NCG);
    const int rem  = blockIdx.x % (BATCH * NCG);
    const int b    = rem / NCG;
    const int d0   = (rem % NCG) * SCB;
    const int d    = d0 + dloc;

    float Ac[4];
    #pragma unroll
    for (int i = 0; i < 4; i++)
        Ac[i] = -__expf(A_log[d * D_STATE + q * 4 + i]);
    float hs[4] = {0.f, 0.f, 0.f, 0.f};
    float sd = 0.f;
    const size_t tbase = (size_t)b * SEQ + (size_t)c * CLEN;

    for (int t0 = 0; t0 < CLEN; t0 += STT) {
        #pragma unroll
        for (int r = 0; r < 8; r++) {
            int e = tid + r * 128; int tt = e >> 5, j = e & 31;
            size_t t = tbase + t0 + tt;
            s_dt[tt][j] = g_dt[t * D_INNER + d0 + j];
            s_u [tt][j] = g_u [t * D_INNER + d0 + j];
        }
        #pragma unroll
        for (int r = 0; r < 4; r++) {
            int e = tid + r * 128; int tt = e >> 4, j = e & 15;
            size_t t = tbase + t0 + tt;
            s_B[tt][j] = xd[t * XPROJ_N + DT_RANK + j];
        }
        __syncthreads();
        #pragma unroll 8
        for (int tt = 0; tt < STT; tt++) {
            float dt = s_dt[tt][dloc];
            float du = dt * s_u[tt][dloc];
            float4 Bq = *(const float4*)&s_B[tt][q * 4];
            hs[0] = fmaf(__expf(dt * Ac[0]), hs[0], du * Bq.x);
            hs[1] = fmaf(__expf(dt * Ac[1]), hs[1], du * Bq.y);
            hs[2] = fmaf(__expf(dt * Ac[2]), hs[2], du * Bq.z);
            hs[3] = fmaf(__expf(dt * Ac[3]), hs[3], du * Bq.w);
            sd += dt;
        }
        __syncthreads();
    }
    size_t idx = (((size_t)c * BATCH + b) * D_INNER + d) * D_STATE + q * 4;
    *(float4*)&g_hend[idx] = make_float4(hs[0], hs[1], hs[2], hs[3]);
    if (q == 0)
        g_sumdt[((size_t)c * BATCH + b) * D_INNER + d] = sd;
}

// ---- S2: sequential chunk fixup --------------------------------------------
__global__ void scan_fixup(const float* __restrict__ A_log)
{
    int i = blockIdx.x * blockDim.x + threadIdx.x;
    if (i >= BATCH * D_INNER * D_STATE) return;
    const int s = i & 15;
    const int d = (i >> 4) % D_INNER;
    const int b = (i >> 4) / D_INNER;
    const float Ac = -__expf(A_log[d * D_STATE + s]);
    float r = 0.f;
    #pragma unroll
    for (int c = 0; c < CHUNKS; c++) {
        g_r[(((size_t)c * BATCH + b) * D_INNER + d) * D_STATE + s] = r;
        if (c + 1 < CHUNKS) {
            size_t idx = (((size_t)c * BATCH + b) * D_INNER + d) * D_STATE + s;
            float P = __expf(Ac * g_sumdt[((size_t)c * BATCH + b) * D_INNER + d]);
            r = fmaf(P, r, g_hend[idx]);
        }
    }
}

// ---- S3: per-chunk full scan seeded with h0 = r_c (v5c body) ---------------
__global__ __launch_bounds__(128)
void scan_part3(const float* __restrict__ A_log,
                const float* __restrict__ Dp,
                const float* __restrict__ xd)
{
    __shared__ __align__(16) float s_dt[STT][SCB];
    __shared__ __align__(16) float s_u [STT][SCB];
    __shared__ __align__(16) float s_z [STT][SCB];
    __shared__ __align__(16) float s_B [STT][D_STATE];
    __shared__ __align__(16) float s_C [STT][D_STATE];

    const int tid  = threadIdx.x;
    const int w    = tid >> 5;
    const int lane = tid & 31;
    const int q    = lane & 3;
    const int chl  = lane >> 2;
    const int dloc = w * 8 + chl;
    const int c    = blockIdx.x / (BATCH * NCG);
    const int rem  = blockIdx.x % (BATCH * NCG);
    const int b    = rem / NCG;
    const int d0   = (rem % NCG) * SCB;
    const int d    = d0 + dloc;

    float Ac[4];
    #pragma unroll
    for (int i = 0; i < 4; i++)
        Ac[i] = -__expf(A_log[d * D_STATE + q * 4 + i]);
    const float Dv = Dp[d];

    float hs[4];
    {
        size_t idx = (((size_t)c * BATCH + b) * D_INNER + d) * D_STATE + q * 4;
        float4 r0 = *(const float4*)&g_r[idx];
        hs[0] = r0.x; hs[1] = r0.y; hs[2] = r0.z; hs[3] = r0.w;
    }

    const size_t tbase = (size_t)b * SEQ + (size_t)c * CLEN;

    for (int t0 = 0; t0 < CLEN; t0 += STT) {
        #pragma unroll
        for (int r = 0; r < 8; r++) {
            int e = tid + r * 128; int tt = e >> 5, j = e & 31;
            size_t t = tbase + t0 + tt;
            s_dt[tt][j] = g_dt[t * D_INNER + d0 + j];
            s_u [tt][j] = g_u [t * D_INNER + d0 + j];
            s_z [tt][j] = g_xz[t * (2 * D_INNER) + D_INNER + d0 + j];
            float v = xd[t * XPROJ_N + DT_RANK + j];
            if (j < D_STATE) s_B[tt][j] = v;
            else             s_C[tt][j - D_STATE] = v;
        }
        __syncthreads();
        #pragma unroll 4
        for (int tt = 0; tt < STT; tt++) {
            float dt = s_dt[tt][dloc];
            float u  = s_u [tt][dloc];
            float du = dt * u;
            float4 Bq = *(const float4*)&s_B[tt][q * 4];
            float4 Cq = *(const float4*)&s_C[tt][q * 4];
            hs[0] = fmaf(__expf(dt * Ac[0]), hs[0], du * Bq.x);
            hs[1] = fmaf(__expf(dt * Ac[1]), hs[1], du * Bq.y);
            hs[2] = fmaf(__expf(dt * Ac[2]), hs[2], du * Bq.z);
            hs[3] = fmaf(__expf(dt * Ac[3]), hs[3], du * Bq.w);
            float p = hs[0] * Cq.x;
            p = fmaf(hs[1], Cq.y, p);
            p = fmaf(hs[2], Cq.z, p);
            p = fmaf(hs[3], Cq.w, p);
            p += __shfl_xor_sync(0xffffffffu, p, 1);
            p += __shfl_xor_sync(0xffffffffu, p, 2);
            if (q == 0) {
                float z = s_z[tt][dloc];
                float sil = __fdividef(z, 1.f + __expf(-z));
                g_y[(tbase + t0 + tt) * D_INNER + d] = (p + u * Dv) * sil;
            }
        }
        __syncthreads();
    }
}

// ---------------- host orchestration ----------------------------------------
extern "C" void kernel_launch(void* const* d_in, const int* in_sizes, int n_in,
                              void* d_out, int out_size)
{
    const float* x         = (const float*)d_in[0];
    const float* in_proj_w = (const float*)d_in[1];
    const float* conv_w    = (const float*)d_in[2];
    const float* conv_b    = (const float*)d_in[3];
    const float* x_proj_w  = (const float*)d_in[4];
    const float* dt_proj_w = (const float*)d_in[5];
    const float* dt_proj_b = (const float*)d_in[6];
    const float* A_log     = (const float*)d_in[7];
    const float* D_param   = (const float*)d_in[8];
    const float* out_proj_w= (const float*)d_in[9];
    const float* ln_w      = (const float*)d_in[10];
    const float* ln_b      = (const float*)d_in[11];
    const float* fnorm_w   = (const float*)d_in[12];
    const float* fnorm_b   = (const float*)d_in[13];
    const float* proj_w    = (const float*)d_in[14];
    const float* proj_b    = (const float*)d_in[15];

    float *h, *xn, *xz, *u, *xd, *dt, *y;
    cudaGetSymbolAddress((void**)&h,  g_h);
    cudaGetSymbolAddress((void**)&xn, g_xn);
    cudaGetSymbolAddress((void**)&xz, g_xz);
    cudaGetSymbolAddress((void**)&u,  g_u);
    cudaGetSymbolAddress((void**)&xd, g_xd);
    cudaGetSymbolAddress((void**)&dt, g_dt);
    cudaGetSymbolAddress((void**)&y,  g_y);

    const int xd_half = NTOK * XPROJ_N;

    cudaMemcpyAsync(h, x, sizeof(float) * (size_t)NTOK * D_MODEL,
                    cudaMemcpyDeviceToDevice);
    zero_kernel<<<(xd_half + 255) / 256, 256>>>(xd, xd_half);
    zero_kernel<<<(xd_half + 255) / 256, 256>>>(xd + xd_half, xd_half);

    dim3 gIn (2 * D_INNER / 128, NTOK / 128, 1);   // 24 x 32
    dim3 gXp (1,                 NTOK / 128, 6);   // N=80, split-K x6
    dim3 gDt (D_INNER / 128,     NTOK / 128, 1);   // 12 x 32
    dim3 gOut(D_MODEL / 128,     NTOK / 128, 1);   //  6 x 32
    const int gScan = CHUNKS * BATCH * NCG;        // 768

    for (int i = 0; i < NLAYER; i++) {
        float* xdi = xd + (size_t)i * xd_half;
        const float* Ai = A_log + (size_t)i * D_INNER * D_STATE;

        ln_kernel<<<NTOK, 256>>>(h, ln_w + i * D_MODEL, ln_b + i * D_MODEL, xn);

        fgemm_kernel<0, false><<<gIn, 256>>>(
            xn, D_MODEL,
            in_proj_w + (size_t)i * 2 * D_INNER * D_MODEL, D_MODEL,
            nullptr, nullptr, xz, 2 * D_INNER, D_MODEL);

        conv_silu_kernel<<<(NTOK * (D_INNER / 4) + 255) / 256, 256>>>(
            conv_w + (size_t)i * D_INNER * D_CONV, conv_b + i * D_INNER);

        fgemm_kernel<0, true><<<gXp, 256>>>(
            u, D_INNER,
            x_proj_w + (size_t)i * XPROJ_N * D_INNER, D_INNER,
            nullptr, nullptr, xdi, XPROJ_N, D_INNER / 6);

        fgemm_kernel<2, false><<<gDt, 256>>>(
            xdi, XPROJ_N,
            dt_proj_w + (size_t)i * D_INNER * DT_RANK, DT_RANK,
            dt_proj_b + i * D_INNER, nullptr, dt, D_INNER, DT_RANK);

        scan_part1<<<gScan, 128>>>(Ai, xdi);
        scan_fixup<<<(BATCH * D_INNER * D_STATE + 255) / 256, 256>>>(Ai);
        scan_part3<<<gScan, 128>>>(Ai, D_param + i * D_INNER, xdi);

        fgemm_kernel<3, false><<<gOut, 256>>>(
            y, D_INNER,
            out_proj_w + (size_t)i * D_MODEL * D_INNER, D_INNER,
            nullptr, h, h, D_MODEL, D_INNER);
    }

    ln_kernel<<<NTOK, 256>>>(h, fnorm_w, fnorm_b, xn);

    fgemm_kernel<1, false><<<gOut, 256>>>(
        xn, D_MODEL, proj_w, D_MODEL, proj_b, nullptr,
        (float*)d_out, D_MODEL, D_MODEL);
}